// round 1
// baseline (speedup 1.0000x reference)
#include <cuda_runtime.h>
#include <cstdint>

// VectorQuantizer: ze [32,64,64,64] f32 -> 131072 rows x 64; embs [1024,64] f32.
// out = concat(zq_st flattened [131072*64], loss scalar).
// zq_st == embs[argmin_dist] numerically; loss = 1.25 * mean((zq-ze)^2).

#define NROWS  131072
#define CDIM   64
#define NE     1024
#define CH     64          // codes staged per smem chunk
#define TPB    128
#define RPT    2           // rows per thread (packed f32x2)
#define RPB    (TPB*RPT)   // 256 rows per block
#define NBLK   (NROWS/RPB) // 512 blocks

typedef unsigned long long ull;

__device__ double g_loss_acc;

__device__ __forceinline__ ull pk2(float lo, float hi) {
    ull d; asm("mov.b64 %0, {%1, %2};" : "=l"(d) : "f"(lo), "f"(hi)); return d;
}
__device__ __forceinline__ void upk2(ull v, float& lo, float& hi) {
    asm("mov.b64 {%0, %1}, %2;" : "=f"(lo), "=f"(hi) : "l"(v));
}
// Packed dual-fp32 FMA (Blackwell f32x2 pipe; ptxas won't auto-fuse, PTX-only)
__device__ __forceinline__ ull ffma2(ull a, ull b, ull c) {
    ull d; asm("fma.rn.f32x2 %0, %1, %2, %3;" : "=l"(d) : "l"(a), "l"(b), "l"(c)); return d;
}

__global__ void vq_zero() { g_loss_acc = 0.0; }

__global__ __launch_bounds__(TPB) void vq_main(
    const float* __restrict__ ze, const float* __restrict__ embs,
    float* __restrict__ out)
{
    __shared__ ull   sE[CH * CDIM];   // duplicated e values: sE[c*64+k] = {e,e}
    __shared__ float sE2[CH];         // per-code squared norms (chunk)
    __shared__ float sred[TPB / 32];

    const int tid = threadIdx.x;
    const long long r0 = (long long)blockIdx.x * RPB + tid * 2;
    const long long r1 = r0 + 1;

    // Load the thread's two z rows, packed as {row0[k], row1[k]}
    ull z2[CDIM];
    {
        const float4* p0 = (const float4*)(ze + r0 * CDIM);
        const float4* p1 = (const float4*)(ze + r1 * CDIM);
        #pragma unroll
        for (int q = 0; q < CDIM / 4; q++) {
            float4 a = p0[q]; float4 b = p1[q];
            z2[4*q+0] = pk2(a.x, b.x);
            z2[4*q+1] = pk2(a.y, b.y);
            z2[4*q+2] = pk2(a.z, b.z);
            z2[4*q+3] = pk2(a.w, b.w);
        }
    }

    // ||z||^2 for both rows (packed self-dot)
    float zn0, zn1;
    {
        ull s = pk2(0.f, 0.f);
        #pragma unroll
        for (int k = 0; k < CDIM; k++) s = ffma2(z2[k], z2[k], s);
        upk2(s, zn0, zn1);
    }

    float best0 = 3.4e38f, best1 = 3.4e38f;
    int bi0 = 0, bi1 = 0;

    for (int ch = 0; ch < NE / CH; ch++) {
        const float* eg = embs + (size_t)ch * CH * CDIM;

        // Stage chunk into smem, each value duplicated into both f32x2 halves
        #pragma unroll
        for (int i = tid; i < CH * CDIM; i += TPB) {
            float v = eg[i];
            sE[i] = pk2(v, v);
        }
        // Per-code squared norms (reads are L1/L2-hot)
        if (tid < CH) {
            float s = 0.f;
            #pragma unroll 8
            for (int k = 0; k < CDIM; k++) { float v = eg[tid * CDIM + k]; s += v * v; }
            sE2[tid] = s;
        }
        __syncthreads();

        const ulonglong2* sEv = (const ulonglong2*)sE;
        for (int g = 0; g < CH; g += 8) {
            ull acc[8];
            #pragma unroll
            for (int c = 0; c < 8; c++) acc[c] = pk2(0.f, 0.f);

            // 8 independent packed dot-product chains; e via broadcast LDS.128
            #pragma unroll
            for (int kp = 0; kp < CDIM / 2; kp++) {
                #pragma unroll
                for (int c = 0; c < 8; c++) {
                    ulonglong2 ev = sEv[(g + c) * (CDIM / 2) + kp];
                    acc[c] = ffma2(z2[2*kp],     ev.x, acc[c]);
                    acc[c] = ffma2(z2[2*kp + 1], ev.y, acc[c]);
                }
            }

            // Distance = (||z||^2 + ||e||^2) - 2*dot  (reference's exact expression)
            #pragma unroll
            for (int c = 0; c < 8; c++) {
                float d0, d1; upk2(acc[c], d0, d1);
                float e2 = sE2[g + c];
                float dist0 = (zn0 + e2) - 2.0f * d0;
                float dist1 = (zn1 + e2) - 2.0f * d1;
                int ci = ch * CH + g + c;
                if (dist0 < best0) { best0 = dist0; bi0 = ci; }  // ascending idx -> first-tie wins
                if (dist1 < best1) { best1 = dist1; bi1 = ci; }
            }
        }
        __syncthreads();
    }

    // Write zq rows + accumulate sum((zq - ze)^2)
    float lsum = 0.f;
    {
        const float4* e0p = (const float4*)(embs + (long long)bi0 * CDIM);
        const float4* e1p = (const float4*)(embs + (long long)bi1 * CDIM);
        float4* o0 = (float4*)(out + r0 * CDIM);
        float4* o1 = (float4*)(out + r1 * CDIM);
        #pragma unroll
        for (int q = 0; q < CDIM / 4; q++) {
            float4 a = e0p[q]; float4 b = e1p[q];
            o0[q] = a; o1[q] = b;
            float zl, zh;
            upk2(z2[4*q+0], zl, zh); { float d = a.x - zl; lsum += d*d; d = b.x - zh; lsum += d*d; }
            upk2(z2[4*q+1], zl, zh); { float d = a.y - zl; lsum += d*d; d = b.y - zh; lsum += d*d; }
            upk2(z2[4*q+2], zl, zh); { float d = a.z - zl; lsum += d*d; d = b.z - zh; lsum += d*d; }
            upk2(z2[4*q+3], zl, zh); { float d = a.w - zl; lsum += d*d; d = b.w - zh; lsum += d*d; }
        }
    }

    // Block reduce -> double atomic accumulate
    #pragma unroll
    for (int off = 16; off > 0; off >>= 1)
        lsum += __shfl_down_sync(0xffffffffu, lsum, off);
    if ((tid & 31) == 0) sred[tid >> 5] = lsum;
    __syncthreads();
    if (tid == 0) {
        float b = 0.f;
        #pragma unroll
        for (int w = 0; w < TPB / 32; w++) b += sred[w];
        atomicAdd(&g_loss_acc, (double)b);
    }
}

__global__ void vq_fin(float* loss_out) {
    // loss = (BETA + 1) * mean((zq - ze)^2), BETA = 0.25
    *loss_out = (float)(1.25 * g_loss_acc / (double)((long long)NROWS * CDIM));
}

extern "C" void kernel_launch(void* const* d_in, const int* in_sizes, int n_in,
                              void* d_out, int out_size) {
    const float* ze   = (const float*)d_in[0];
    const float* embs = (const float*)d_in[1];
    float* out = (float*)d_out;

    vq_zero<<<1, 1>>>();
    vq_main<<<NBLK, TPB>>>(ze, embs, out);
    if (out_size > NROWS * CDIM)
        vq_fin<<<1, 1>>>(out + (out_size - 1));
}

// round 2
// speedup vs baseline: 2.3873x; 2.3873x over previous
#include <cuda_runtime.h>
#include <cstdint>

// VectorQuantizer on GB300: fused 131072x1024x64 fp32 distance-GEMM + argmin,
// f32x2 packed-FMA SIMT path, smem-tiled (128 rows x 64-code chunks), cp.async
// double-buffered codebook staging, pre-transposed/duplicated codebook.

#define NROWS  131072
#define CDIM   64
#define NE     1024
#define TPB    128
#define RPB    128                 // rows per block
#define NBLK   (NROWS/RPB)         // 1024
#define CH     64                  // codes per smem chunk
#define NCH    (NE/CH)             // 16

typedef unsigned long long ull;

__device__ ull    g_eTd[CDIM * NE];  // [k][c] -> {e,e}  (512KB)
__device__ ull    g_e2d[NE];         // {||e||^2, ||e||^2}
__device__ double g_loss_acc;

__device__ __forceinline__ ull pk2(float lo, float hi) {
    ull d; asm("mov.b64 %0, {%1, %2};" : "=l"(d) : "f"(lo), "f"(hi)); return d;
}
__device__ __forceinline__ void upk2(ull v, float& lo, float& hi) {
    asm("mov.b64 {%0, %1}, %2;" : "=f"(lo), "=f"(hi) : "l"(v));
}
__device__ __forceinline__ ull ffma2(ull a, ull b, ull c) {
    ull d; asm("fma.rn.f32x2 %0, %1, %2, %3;" : "=l"(d) : "l"(a), "l"(b), "l"(c)); return d;
}
__device__ __forceinline__ ull add2(ull a, ull b) {
    ull d; asm("add.rn.f32x2 %0, %1, %2;" : "=l"(d) : "l"(a), "l"(b)); return d;
}
__device__ __forceinline__ void cpa16(void* dst, const void* src) {
    unsigned sd = (unsigned)__cvta_generic_to_shared(dst);
    asm volatile("cp.async.cg.shared.global [%0], [%1], 16;" :: "r"(sd), "l"(src));
}

// Prologue 1: transpose + duplicate codebook into g_eTd; zero loss acc.
__global__ void vq_prep(const float* __restrict__ embs) {
    int idx = blockIdx.x * 256 + threadIdx.x;      // = c*64 + k (coalesced read)
    if (idx == 0) g_loss_acc = 0.0;
    float v = embs[idx];
    int c = idx >> 6, k = idx & 63;
    g_eTd[k * NE + c] = pk2(v, v);
}

// Prologue 2: per-code squared norms (duplicated).
__global__ void vq_prep2(const float* __restrict__ embs) {
    int c = blockIdx.x * 128 + threadIdx.x;
    const float4* p = (const float4*)(embs + (size_t)c * CDIM);
    float s = 0.f;
    #pragma unroll
    for (int q = 0; q < 16; q++) {
        float4 v = p[q];
        s += v.x * v.x + v.y * v.y + v.z * v.z + v.w * v.w;
    }
    g_e2d[c] = pk2(s, s);
}

// smem layout (ull units):
//  sED  [2][64][64]  : 8192 ull   e chunk, duplicated, double-buffered
//  sE2  [2][64]      :  128 ull
//  zT   [64][64]     : 4096 ull   zT[k][rp] = {z[2rp][k], z[2rp+1][k]}
//  szn  [128] floats :   64 ull
//  sred [4]  floats  :    2 ull
#define SMEM_ULL  (8192 + 128 + 4096 + 64 + 2)
#define SMEM_B    (SMEM_ULL * 8)

__global__ __launch_bounds__(TPB) void vq_main(
    const float* __restrict__ ze, const float* __restrict__ embs,
    float* __restrict__ out)
{
    extern __shared__ ull sm[];
    ull*   sED  = sm;                       // [2][4096]
    ull*   sE2  = sm + 8192;                // [2][64]
    ull*   zTu  = sm + 8320;                // [64][64]
    float* zTf  = (float*)zTu;              // [64][128]
    float* sznf = (float*)(sm + 8320 + 4096);
    float* sred = sznf + 128;

    const int tid = threadIdx.x;
    const int rg  = tid & 15;               // row-group (16)
    const int cg  = tid >> 4;               // code-group (8) -> phase-broadcast e loads
    const size_t row0 = (size_t)blockIdx.x * RPB;

    // kick off chunk-0 codebook load (coalesced LDGSTS from pre-transposed layout)
    #pragma unroll
    for (int i = 0; i < 16; i++) {
        int lin = i * TPB + tid;            // 0..2047
        int k = lin >> 5, c2 = lin & 31;
        cpa16(&sED[k * 64 + c2 * 2], &g_eTd[k * NE + c2 * 2]);
    }
    if (tid < 32) cpa16(&sE2[tid * 2], &g_e2d[tid * 2]);
    asm volatile("cp.async.commit_group;");

    // z tile: transpose into smem + row norms
    {
        const float4* zr = (const float4*)(ze + (row0 + tid) * CDIM);
        float zn = 0.f;
        #pragma unroll
        for (int q = 0; q < 16; q++) {
            float4 v = zr[q];
            zTf[(4 * q + 0) * TPB + tid] = v.x;
            zTf[(4 * q + 1) * TPB + tid] = v.y;
            zTf[(4 * q + 2) * TPB + tid] = v.z;
            zTf[(4 * q + 3) * TPB + tid] = v.w;
            zn += v.x * v.x + v.y * v.y + v.z * v.z + v.w * v.w;
        }
        sznf[tid] = zn;
    }
    __syncthreads();

    ull znj[4];
    #pragma unroll
    for (int j = 0; j < 4; j++) znj[j] = ((const ull*)sznf)[rg * 4 + j];

    float best[8]; int bidx[8];
    #pragma unroll
    for (int i = 0; i < 8; i++) { best[i] = 3.4e38f; bidx[i] = 0; }

    const ull  M2 = pk2(-2.f, -2.f);
    const ull* zp = zTu + rg * 4;

    for (int ch = 0; ch < NCH; ch++) {
        const int b = ch & 1;
        if (ch + 1 < NCH) {
            const int nb = (ch + 1) & 1;
            #pragma unroll
            for (int i = 0; i < 16; i++) {
                int lin = i * TPB + tid;
                int k = lin >> 5, c2 = lin & 31;
                cpa16(&sED[nb * 4096 + k * 64 + c2 * 2],
                      &g_eTd[k * NE + (ch + 1) * CH + c2 * 2]);
            }
            if (tid < 32) cpa16(&sE2[nb * 64 + tid * 2], &g_e2d[(ch + 1) * CH + tid * 2]);
            asm volatile("cp.async.commit_group;");
            asm volatile("cp.async.wait_group 1;");
        } else {
            asm volatile("cp.async.wait_group 0;");
        }
        __syncthreads();

        const ull* ep = sED + b * 4096 + cg * 8;
        ull acc[4][8];
        #pragma unroll
        for (int j = 0; j < 4; j++)
            #pragma unroll
            for (int c = 0; c < 8; c++) acc[j][c] = 0ull;

        // 32 FFMA2 : 6 LDS.128 per k; e loads broadcast within each phase
        #pragma unroll 8
        for (int k = 0; k < CDIM; k++) {
            const ulonglong2* zk = (const ulonglong2*)(zp + k * 64);
            const ulonglong2* ek = (const ulonglong2*)(ep + k * 64);
            ulonglong2 za = zk[0], zb = zk[1];
            ulonglong2 e0 = ek[0], e1 = ek[1], e2v = ek[2], e3 = ek[3];
            ull zr_[4] = { za.x, za.y, zb.x, zb.y };
            ull er_[8] = { e0.x, e0.y, e1.x, e1.y, e2v.x, e2v.y, e3.x, e3.y };
            #pragma unroll
            for (int j = 0; j < 4; j++)
                #pragma unroll
                for (int c = 0; c < 8; c++)
                    acc[j][c] = ffma2(zr_[j], er_[c], acc[j][c]);
        }

        // dist = (||z||^2 + ||e||^2) - 2*dot ; strict < + ascending index
        const ull* e2p = sE2 + b * 64 + cg * 8;
        #pragma unroll
        for (int c = 0; c < 8; c++) {
            ull e2d = e2p[c];
            int ci  = ch * CH + cg * 8 + c;
            #pragma unroll
            for (int j = 0; j < 4; j++) {
                ull d2 = ffma2(acc[j][c], M2, add2(znj[j], e2d));
                float dlo, dhi; upk2(d2, dlo, dhi);
                if (dlo < best[j * 2])     { best[j * 2]     = dlo; bidx[j * 2]     = ci; }
                if (dhi < best[j * 2 + 1]) { best[j * 2 + 1] = dhi; bidx[j * 2 + 1] = ci; }
            }
        }
        __syncthreads();   // protect buffer b before it gets reloaded at ch+2
    }

    // cross code-group reduction (8 cgs per row), reuse sED
    float* resf = (float*)sED;          // [8][128]
    int*   resi = (int*)(sED + 512);    // [8][128]
    #pragma unroll
    for (int rl = 0; rl < 8; rl++) {
        int r = rg * 8 + rl;
        resf[cg * 128 + r] = best[rl];
        resi[cg * 128 + r] = bidx[rl];
    }
    __syncthreads();

    float bv = resf[tid]; int bi = resi[tid];
    #pragma unroll
    for (int g2 = 1; g2 < 8; g2++) {
        float v = resf[g2 * 128 + tid];
        int  ii = resi[g2 * 128 + tid];
        if (v < bv || (v == bv && ii < bi)) { bv = v; bi = ii; }
    }

    // gather zq, write out, accumulate loss
    const float4* ep4 = (const float4*)(embs + (size_t)bi * CDIM);
    float4* op = (float4*)(out + (row0 + tid) * CDIM);
    float ls = 0.f;
    #pragma unroll
    for (int q = 0; q < 16; q++) {
        float4 e = ep4[q];
        float d0 = e.x - zTf[(4 * q + 0) * TPB + tid];
        float d1 = e.y - zTf[(4 * q + 1) * TPB + tid];
        float d2 = e.z - zTf[(4 * q + 2) * TPB + tid];
        float d3 = e.w - zTf[(4 * q + 3) * TPB + tid];
        ls += d0 * d0 + d1 * d1 + d2 * d2 + d3 * d3;
        op[q] = e;
    }
    #pragma unroll
    for (int off = 16; off > 0; off >>= 1)
        ls += __shfl_down_sync(0xffffffffu, ls, off);
    if ((tid & 31) == 0) sred[tid >> 5] = ls;
    __syncthreads();
    if (tid == 0)
        atomicAdd(&g_loss_acc, (double)(sred[0] + sred[1] + sred[2] + sred[3]));
}

__global__ void vq_fin(float* loss_out) {
    *loss_out = (float)(1.25 * g_loss_acc / (double)((long long)NROWS * CDIM));
}

extern "C" void kernel_launch(void* const* d_in, const int* in_sizes, int n_in,
                              void* d_out, int out_size) {
    const float* ze   = (const float*)d_in[0];
    const float* embs = (const float*)d_in[1];
    float* out = (float*)d_out;

    static_assert(SMEM_B < 112 * 1024, "2 blocks/SM budget");
    cudaFuncSetAttribute(vq_main, cudaFuncAttributeMaxDynamicSharedMemorySize, SMEM_B);

    vq_prep<<<NE * CDIM / 256, 256>>>(embs);
    vq_prep2<<<NE / 128, 128>>>(embs);
    vq_main<<<NBLK, TPB, SMEM_B>>>(ze, embs, out);
    if (out_size > NROWS * CDIM)
        vq_fin<<<1, 1>>>(out + (out_size - 1));
}